// round 11
// baseline (speedup 1.0000x reference)
#include <cuda_runtime.h>
#include <math.h>

#define NT 365
#define NTP 368          // 23 chunks of 16
#define NCHUNK 23
#define CH 16
#define RPITCH 36        // reduce-buffer row pitch (conflict-free float4 reads)
#define NS 1024
#define NH 64
#define NG 32
#define NW 514           // NH*8 + 2
#define WPITCH 520       // g_w row pitch

#define NB_GEMM 288      // 32 site-tiles x 9 row-tiles
#define NB_TRAN 384      // 32 site-tiles x 12 t-tiles

__device__ float  g_w[NS * WPITCH];   // gate pre-activations
__device__ float4 g_f[NS * NTP];      // transposed, preprocessed forcing [s][t]
__device__ float  g_pA[NT * NS];      // partial Y, h in [0,32)  (+qb)
__device__ float  g_pB[NT * NS];      // partial Y, h in [32,64)

__device__ __forceinline__ float sigm(float x) { return 1.0f / (1.0f + expf(-x)); }

// ---------------------------------------------------------------------------
// Prep kernel: 672 blocks x 256 threads.
//  blocks [0, 288):   GEMM  w = xc @ fc_w.T + fc_b  (32-site x 64-row tiles,
//                     2x4 per thread, k=32)
//  blocks [288, 672): transpose+transform x[t][s] -> g_f[s][t] with the
//                     rain/snow partition and ReLU(Ta) precomputed.
// The two block types co-schedule on the SMs and hide each other's latency.
// ---------------------------------------------------------------------------
__global__ void __launch_bounds__(256)
prep_kernel(const float* __restrict__ x,
            const float* __restrict__ xc,
            const float* __restrict__ fc_w,
            const float* __restrict__ fc_b) {
    __shared__ __align__(16) char smemRaw[16896];

    const int tid = threadIdx.x;
    const int bid = blockIdx.x;

    if (bid < NB_GEMM) {
        // ---------------- GEMM branch ----------------
        float* sX = reinterpret_cast<float*>(smemRaw);            // [32][36]
        float* sF = sX + 32 * 36;                                 // [32][68]

        const int s0 = (bid & 31) << 5;     // 32-site tile
        const int j0 = (bid >> 5) << 6;     // 64-row tile (9 tiles)

        #pragma unroll
        for (int i = 0; i < 4; ++i) {       // stage xc^T
            const int idx = tid + (i << 8);
            const int k   = idx & 31;
            const int sl  = idx >> 5;       // 0..31
            sX[k * 36 + sl] = xc[(s0 + sl) * NG + k];
        }
        #pragma unroll
        for (int i = 0; i < 8; ++i) {       // stage fc_w^T
            const int idx = tid + (i << 8);
            const int k   = idx & 31;
            const int jl  = idx >> 5;       // 0..63
            const int j   = j0 + jl;
            sF[k * 68 + jl] = (j < NW) ? fc_w[j * NG + k] : 0.0f;
        }
        __syncthreads();

        const int ts = tid >> 4;            // 0..15 -> site pair
        const int tj = tid & 15;            // 0..15 -> row quad
        const int sp = ts << 1;
        const int rb = tj << 2;

        float acc[2][4];
        #pragma unroll
        for (int a = 0; a < 2; ++a)
            #pragma unroll
            for (int b = 0; b < 4; ++b) acc[a][b] = 0.0f;

        #pragma unroll
        for (int k = 0; k < 32; ++k) {
            const float2 xs = *reinterpret_cast<const float2*>(sX + k * 36 + sp);
            const float4 fj = *reinterpret_cast<const float4*>(sF + k * 68 + rb);
            const float xa[2] = {xs.x, xs.y};
            const float fb[4] = {fj.x, fj.y, fj.z, fj.w};
            #pragma unroll
            for (int a = 0; a < 2; ++a)
                #pragma unroll
                for (int b = 0; b < 4; ++b)
                    acc[a][b] = fmaf(xa[a], fb[b], acc[a][b]);
        }

        float bias[4];
        #pragma unroll
        for (int b = 0; b < 4; ++b) {
            const int j = j0 + rb + b;
            bias[b] = (j < NW) ? fc_b[j] : 0.0f;
        }
        #pragma unroll
        for (int a = 0; a < 2; ++a) {
            const int sg = s0 + sp + a;
            #pragma unroll
            for (int b = 0; b < 4; ++b) {
                const int j = j0 + rb + b;
                if (j < NW) g_w[sg * WPITCH + j] = acc[a][b] + bias[b];
            }
        }
    } else {
        // ---------------- transpose + transform branch ----------------
        float* sPs = reinterpret_cast<float*>(smemRaw);   // [32][33] each
        float* sPl = sPs + 32 * 33;
        float* sTa = sPl + 32 * 33;
        float* sE  = sTa + 32 * 33;

        const int b2 = bid - NB_GEMM;       // 0..383
        const int t0 = (b2 % 12) << 5;      // t tile
        const int s0 = (b2 / 12) << 5;      // s tile
        const int r  = tid >> 5;            // base row (t_local), +8 per iter
        const int ln = tid & 31;

        const float4* x4 = reinterpret_cast<const float4*>(x);
        #pragma unroll
        for (int i = 0; i < 4; ++i) {
            const int tl = r + (i << 3);    // t_local 0..31
            const int t  = t0 + tl;
            float Ps = 0.f, Pl = 0.f, rT = 0.f, Ev = 0.f;
            if (t < NT) {
                float4 xi = x4[t * NS + s0 + ln];   // coalesced
                float P = xi.x, E = xi.y, T1 = xi.z, T2 = xi.w;
                float Ta = (T1 + T2) * 0.5f;
                bool valid  = (T1 < 0.0f) && (T2 > 0.0f);
                float denom = valid ? (T2 - T1) : 1.0f;
                float ratio = valid ? (T1 + T2) / denom : 0.0f;
                ratio = fminf(fmaxf(ratio, -0.999999f), 0.999999f);
                float rP = 1.0f - acosf(ratio) / 3.1415f;
                if (T1 >= 0.0f) rP = 1.0f;
                if (T2 <= 0.0f) rP = 0.0f;
                Ps = (1.0f - rP) * P;
                Pl = rP * P;
                rT = fmaxf(Ta, 0.0f);
                Ev = E;
            }
            sPs[tl * 33 + ln] = Ps;
            sPl[tl * 33 + ln] = Pl;
            sTa[tl * 33 + ln] = rT;
            sE [tl * 33 + ln] = Ev;
        }
        __syncthreads();
        #pragma unroll
        for (int i = 0; i < 4; ++i) {
            const int sl = r + (i << 3);    // s_local 0..31
            const int t  = t0 + ln;
            if (t < NTP) {
                float4 o;
                o.x = sPs[ln * 33 + sl];    // bank (ln+sl)%32: conflict-free
                o.y = sPl[ln * 33 + sl];
                o.z = sTa[ln * 33 + sl];
                o.w = sE [ln * 33 + sl];
                g_f[(s0 + sl) * NTP + t] = o;   // coalesced in t
            }
        }
    }
}

// ---------------------------------------------------------------------------
// Scan: 1024 blocks x 64 threads (2 independent warps; warp0 -> g_pA(+qb),
// warp1 -> g_pB). Coalesced staging from g_f. Reduce(c-1) interleaved BEFORE
// body(c) so its LDS latencies overlap the body's carry chain.
// ---------------------------------------------------------------------------
__global__ void __launch_bounds__(64)
scan_kernel(float* __restrict__ dummy) {
    __shared__ float4 sForc[NTP];                 // 5888 B
    __shared__ float  sBuf[2][2][CH * RPITCH];    // 9216 B  [warp][parity]
    __shared__ float  sMax[2], sSum[2];

    const int tid  = threadIdx.x;
    const int warp = tid >> 5;
    const int lane = tid & 31;
    const int s    = blockIdx.x;

    // ---- coalesced staging of preprocessed forcing ----
    const float4* frow = g_f + s * NTP;
    for (int t = tid; t < NTP; t += 64) sForc[t] = frow[t];

    // ---- load pre-activations (coalesced, 9 lines) ----
    const float* wrow = g_w + s * WPITCH;
    float wv[8];
    #pragma unroll
    for (int c = 0; c < 8; ++c) wv[c] = wrow[c * 64 + tid];
    const float qb = fmaxf(wrow[513], 0.0f) * (1.0f / 64.0f);

    // ---- activations (h = tid) ----
    const float gm   = expf(wv[0]) + 1.0f;
    const float nge  = -2.0f * sigm(wv[1]);
    const float go   = sigm(wv[2]);
    const float gl   = expf(2.0f * wv[3]);
    const float araw = wv[4];
    const float gb   = sigm(wv[5]);
    const float kb   = sigm(wv[6]) * 0.1f;
    const float gi   = sigm(wv[7]);
    const float kb1  = 1.0f - kb;

    // ---- softmax over 64 h across the 2 warps ----
    float m = araw;
    #pragma unroll
    for (int o = 16; o; o >>= 1) m = fmaxf(m, __shfl_xor_sync(0xffffffffu, m, o));
    if (lane == 0) sMax[warp] = m;
    __syncthreads();
    m = fmaxf(sMax[0], sMax[1]);
    float e = expf(araw - m);
    float ssum = e;
    #pragma unroll
    for (int o = 16; o; o >>= 1) ssum += __shfl_xor_sync(0xffffffffu, ssum, o);
    if (lane == 0) sSum[warp] = ssum;
    __syncthreads();
    const float ga = e / (sSum[0] + sSum[1]);

    const float chc  = go * (1.0f - gb) * ga - ga;
    const float cg   = kb * ga;
    const float gogb = go * gb;
    const float qbw  = (warp == 0) ? qb : 0.0f;

    float* outHalf = (warp == 0) ? g_pA : g_pB;
    const int rt = lane >> 1;
    const int rq = lane & 1;

    float S0 = 0.0f, H0 = 0.0f, G0 = 0.0f;

    auto body = [&](int c) {
        float* buf = sBuf[warp][c & 1];
        const float4* fp = sForc + c * CH;
        float yv[CH];
        #pragma unroll
        for (int tt = 0; tt < CH; ++tt) {
            float4 f  = fp[tt];
            float Sm  = fminf(S0, f.z * gm);
            float At  = fmaf(f.w, nge, f.y * gi);
            float H   = fmaxf(H0 + Sm + At, 0.0f);
            float Hc  = fminf(H, gl);
            float t1  = fmaf(-go, Hc, H);
            float g2  = fmaf(Hc, gogb, G0);
            H0 = fminf(t1, gl);
            G0 = g2 * kb1;
            S0 = (S0 - Sm) + f.x;
            float y = H * ga;
            y = fmaf(Hc, chc, y);
            y = fmaf(g2, cg, y);
            yv[tt] = y;
        }
        #pragma unroll
        for (int tt = 0; tt < CH; ++tt)
            buf[tt * RPITCH + lane] = yv[tt];
    };

    auto reduceC = [&](int rc) {
        const float* bb = sBuf[warp][rc & 1];
        const float4* rr = reinterpret_cast<const float4*>(bb + rt * RPITCH + rq * 16);
        float4 v0 = rr[0], v1 = rr[1], v2 = rr[2], v3 = rr[3];
        float p = (((v0.x + v0.y) + (v0.z + v0.w)) + ((v1.x + v1.y) + (v1.z + v1.w)))
                + (((v2.x + v2.y) + (v2.z + v2.w)) + ((v3.x + v3.y) + (v3.z + v3.w)));
        p += __shfl_xor_sync(0xffffffffu, p, 1);
        const int tg = rc * CH + rt;
        if (rq == 0 && tg < NT) outHalf[tg * NS + s] = p + qbw;
    };

    body(0);
    __syncwarp();
    for (int c = 1; c < NCHUNK; ++c) {
        reduceC(c - 1);    // independent of the carry chain -> interleaves
        body(c);
        __syncwarp();
    }
    reduceC(NCHUNK - 1);
    (void)dummy;
}

// ---------------------------------------------------------------------------
// Combine: out = pA + pB (qb folded into pA). float4, coalesced.
// ---------------------------------------------------------------------------
__global__ void __launch_bounds__(256)
combine_kernel(float* __restrict__ out) {
    const int idx = blockIdx.x * 256 + threadIdx.x;
    float4 a = reinterpret_cast<const float4*>(g_pA)[idx];
    float4 b = reinterpret_cast<const float4*>(g_pB)[idx];
    float4 o;
    o.x = a.x + b.x;
    o.y = a.y + b.y;
    o.z = a.z + b.z;
    o.w = a.w + b.w;
    reinterpret_cast<float4*>(out)[idx] = o;
}

// ---------------------------------------------------------------------------
extern "C" void kernel_launch(void* const* d_in, const int* in_sizes, int n_in,
                              void* d_out, int out_size) {
    const float* x    = (const float*)d_in[0];   // [NT, NS, 4]
    const float* xc   = (const float*)d_in[1];   // [NS, NG]
    const float* fc_w = (const float*)d_in[2];   // [NW, NG]
    const float* fc_b = (const float*)d_in[3];   // [NW]
    float* out = (float*)d_out;                  // [NT, NS]

    prep_kernel<<<NB_GEMM + NB_TRAN, 256>>>(x, xc, fc_w, fc_b);
    scan_kernel<<<NS, 64>>>(out);
    combine_kernel<<<NT, 256>>>(out);
}

// round 12
// speedup vs baseline: 1.5811x; 1.5811x over previous
#include <cuda_runtime.h>
#include <math.h>

#define NT 365
#define NTP 368          // 23 chunks of 16
#define NCHUNK 23
#define CH 16
#define RPITCH 36        // reduce-buffer row pitch (conflict-free float4 reads)
#define NS 1024
#define NH 64
#define NG 32
#define NW 514           // NH*8 + 2
#define WPITCH 520       // g_w row pitch

__device__ float g_w[NS * WPITCH];   // pre-activations w[s][j]
__device__ float g_pA[NT * NS];      // partial Y, h in [0,32)  (+qb)
__device__ float g_pB[NT * NS];      // partial Y, h in [32,64)

__device__ __forceinline__ float sigm(float x) { return 1.0f / (1.0f + expf(-x)); }

// ---------------------------------------------------------------------------
// GEMM: w[s][j] = xc[s,:] . fc_w[j,:] + fc_b[j].
// 288 blocks = 32 site-tiles (32 sites) x 9 row-tiles (64 rows); 256 threads;
// each thread computes 2x4 with K=32 (320 instr vs R10's 1088 -> latency-
// bound fix: 2 blocks/SM, 3.4x shorter serial chain).
// Tiles staged transposed; conflict-free pitches (36 / 68).
// ---------------------------------------------------------------------------
__global__ void __launch_bounds__(256)
gemm_kernel(const float* __restrict__ xc,
            const float* __restrict__ fc_w,
            const float* __restrict__ fc_b) {
    __shared__ float sX[32 * 36];   // [k][site_loc]
    __shared__ float sF[32 * 68];   // [k][row_loc]

    const int tid = threadIdx.x;
    const int s0  = (blockIdx.x & 31) << 5;   // site tile base
    const int j0  = (blockIdx.x >> 5) << 6;   // row tile base (0..8)

    #pragma unroll
    for (int i = 0; i < 4; ++i) {             // stage xc^T (32x32)
        const int idx = tid + (i << 8);
        const int k   = idx & 31;
        const int sl  = idx >> 5;
        sX[k * 36 + sl] = xc[(s0 + sl) * NG + k];
    }
    #pragma unroll
    for (int i = 0; i < 8; ++i) {             // stage fc_w^T (32x64)
        const int idx = tid + (i << 8);
        const int k   = idx & 31;
        const int jl  = idx >> 5;
        const int j   = j0 + jl;
        sF[k * 68 + jl] = (j < NW) ? fc_w[j * NG + k] : 0.0f;
    }
    __syncthreads();

    const int ts = tid >> 4;                  // 0..15 -> site pair
    const int tj = tid & 15;                  // 0..15 -> row quad
    const int sp = ts << 1;
    const int rb = tj << 2;

    float acc[2][4];
    #pragma unroll
    for (int a = 0; a < 2; ++a)
        #pragma unroll
        for (int b = 0; b < 4; ++b) acc[a][b] = 0.0f;

    #pragma unroll
    for (int k = 0; k < 32; ++k) {
        const float2 xs = *reinterpret_cast<const float2*>(sX + k * 36 + sp);
        const float4 fj = *reinterpret_cast<const float4*>(sF + k * 68 + rb);
        const float xa[2] = {xs.x, xs.y};
        const float fb[4] = {fj.x, fj.y, fj.z, fj.w};
        #pragma unroll
        for (int a = 0; a < 2; ++a)
            #pragma unroll
            for (int b = 0; b < 4; ++b)
                acc[a][b] = fmaf(xa[a], fb[b], acc[a][b]);
    }

    float bias[4];
    #pragma unroll
    for (int b = 0; b < 4; ++b) {
        const int j = j0 + rb + b;
        bias[b] = (j < NW) ? fc_b[j] : 0.0f;
    }
    #pragma unroll
    for (int a = 0; a < 2; ++a) {
        const int sg = s0 + sp + a;
        #pragma unroll
        for (int b = 0; b < 4; ++b) {
            const int j = j0 + rb + b;
            if (j < NW) g_w[sg * WPITCH + j] = acc[a][b] + bias[b];
        }
    }
}

// ---------------------------------------------------------------------------
// Scan (identical to R10 best): 1024 blocks x 64 threads; 2 independent
// warps (warp0 -> g_pA(+qb), warp1 -> g_pB); zero in-loop block barriers;
// chunked y buffering + float4 transpose-reduce per warp.
// ---------------------------------------------------------------------------
__global__ void __launch_bounds__(64)
scan_kernel(const float* __restrict__ x) {
    __shared__ float4 sForc[NTP];                 // 5888 B
    __shared__ float  sBuf[2][2][CH * RPITCH];    // 9216 B  [warp][parity]
    __shared__ float  sMax[2], sSum[2];

    const int tid  = threadIdx.x;
    const int warp = tid >> 5;
    const int lane = tid & 31;
    const int s    = blockIdx.x;

    // ---- load this site's pre-activations (coalesced, 9 lines) ----
    const float* wrow = g_w + s * WPITCH;
    float wv[8];
    #pragma unroll
    for (int c = 0; c < 8; ++c) wv[c] = wrow[c * 64 + tid];
    const float qb = fmaxf(wrow[513], 0.0f) * (1.0f / 64.0f);

    // ---- stage forcing + rain/snow partition; .z = ReLU(Ta) ----
    const float4* x4 = reinterpret_cast<const float4*>(x);
    for (int t = tid; t < NTP; t += 64) {
        float4 o = make_float4(0.f, 0.f, 0.f, 0.f);
        if (t < NT) {
            float4 xi = x4[t * NS + s];
            float P = xi.x, E = xi.y, T1 = xi.z, T2 = xi.w;
            float Ta = (T1 + T2) * 0.5f;
            bool valid  = (T1 < 0.0f) && (T2 > 0.0f);
            float denom = valid ? (T2 - T1) : 1.0f;
            float ratio = valid ? (T1 + T2) / denom : 0.0f;
            ratio = fminf(fmaxf(ratio, -0.999999f), 0.999999f);
            float rP = 1.0f - acosf(ratio) / 3.1415f;
            if (T1 >= 0.0f) rP = 1.0f;
            if (T2 <= 0.0f) rP = 0.0f;
            o.x = (1.0f - rP) * P;       // Ps
            o.y = rP * P;                // Pl
            o.z = fmaxf(Ta, 0.0f);       // ReLU(Ta)
            o.w = E;
        }
        sForc[t] = o;
    }

    // ---- activations (h = tid) ----
    const float gm   = expf(wv[0]) + 1.0f;
    const float nge  = -2.0f * sigm(wv[1]);
    const float go   = sigm(wv[2]);
    const float gl   = expf(2.0f * wv[3]);
    const float araw = wv[4];
    const float gb   = sigm(wv[5]);
    const float kb   = sigm(wv[6]) * 0.1f;
    const float gi   = sigm(wv[7]);
    const float kb1  = 1.0f - kb;

    // ---- softmax over 64 h across the 2 warps ----
    float m = araw;
    #pragma unroll
    for (int o = 16; o; o >>= 1) m = fmaxf(m, __shfl_xor_sync(0xffffffffu, m, o));
    if (lane == 0) sMax[warp] = m;
    __syncthreads();
    m = fmaxf(sMax[0], sMax[1]);
    float e = expf(araw - m);
    float ssum = e;
    #pragma unroll
    for (int o = 16; o; o >>= 1) ssum += __shfl_xor_sync(0xffffffffu, ssum, o);
    if (lane == 0) sSum[warp] = ssum;
    __syncthreads();
    const float ga = e / (sSum[0] + sSum[1]);

    const float chc  = go * (1.0f - gb) * ga - ga;   // coeff of Hc in y
    const float cg   = kb * ga;                      // coeff of g2 in y
    const float gogb = go * gb;
    const float qbw  = (warp == 0) ? qb : 0.0f;      // qb folded into pA

    float* outHalf = (warp == 0) ? g_pA : g_pB;
    const int rt = lane >> 1;
    const int rq = lane & 1;

    float S0 = 0.0f, H0 = 0.0f, G0 = 0.0f;

    for (int c = 0; c < NCHUNK; ++c) {
        float* buf = sBuf[warp][c & 1];
        const float4* fp = sForc + c * CH;
        float yv[CH];
        #pragma unroll
        for (int tt = 0; tt < CH; ++tt) {
            float4 f  = fp[tt];                      // broadcast LDS.128
            float Sm  = fminf(S0, f.z * gm);
            float At  = fmaf(f.w, nge, f.y * gi);    // Pl*gi - E*ge
            float H   = fmaxf(H0 + Sm + At, 0.0f);
            float Hc  = fminf(H, gl);
            float t1  = fmaf(-go, Hc, H);
            float g2  = fmaf(Hc, gogb, G0);
            H0 = fminf(t1, gl);
            G0 = g2 * kb1;
            S0 = (S0 - Sm) + f.x;
            float y = H * ga;
            y = fmaf(Hc, chc, y);
            y = fmaf(g2, cg, y);
            yv[tt] = y;
        }
        #pragma unroll
        for (int tt = 0; tt < CH; ++tt)
            buf[tt * RPITCH + lane] = yv[tt];        // burst, conflict-free
        __syncwarp();
        const float4* rr = reinterpret_cast<const float4*>(buf + rt * RPITCH + rq * 16);
        float4 v0 = rr[0], v1 = rr[1], v2 = rr[2], v3 = rr[3];
        float p = (((v0.x + v0.y) + (v0.z + v0.w)) + ((v1.x + v1.y) + (v1.z + v1.w)))
                + (((v2.x + v2.y) + (v2.z + v2.w)) + ((v3.x + v3.y) + (v3.z + v3.w)));
        p += __shfl_xor_sync(0xffffffffu, p, 1);
        const int tg = c * CH + rt;
        if (rq == 0 && tg < NT) outHalf[tg * NS + s] = p + qbw;
    }
}

// ---------------------------------------------------------------------------
// Combine: out[t][s] = pA + pB  (qb already folded into pA). float4, coalesced.
// ---------------------------------------------------------------------------
__global__ void __launch_bounds__(256)
combine_kernel(float* __restrict__ out) {
    const int idx = blockIdx.x * 256 + threadIdx.x;   // NT*NS/4 elements
    float4 a = reinterpret_cast<const float4*>(g_pA)[idx];
    float4 b = reinterpret_cast<const float4*>(g_pB)[idx];
    float4 o;
    o.x = a.x + b.x;
    o.y = a.y + b.y;
    o.z = a.z + b.z;
    o.w = a.w + b.w;
    reinterpret_cast<float4*>(out)[idx] = o;
}

// ---------------------------------------------------------------------------
extern "C" void kernel_launch(void* const* d_in, const int* in_sizes, int n_in,
                              void* d_out, int out_size) {
    const float* x    = (const float*)d_in[0];   // [NT, NS, 4]
    const float* xc   = (const float*)d_in[1];   // [NS, NG]
    const float* fc_w = (const float*)d_in[2];   // [NW, NG]
    const float* fc_b = (const float*)d_in[3];   // [NW]
    float* out = (float*)d_out;                  // [NT, NS]

    gemm_kernel<<<288, 256>>>(xc, fc_w, fc_b);
    scan_kernel<<<NS, 64>>>(x);
    combine_kernel<<<NT, 256>>>(out);
}

// round 13
// speedup vs baseline: 1.6785x; 1.0616x over previous
#include <cuda_runtime.h>
#include <math.h>

#define NT 365
#define NTP 368          // 23 chunks of 16
#define NCHUNK 23
#define CH 16
#define RPITCH 36        // reduce-buffer row pitch (conflict-free float4 reads)
#define NS 1024
#define NH 64
#define NG 32
#define NW 514           // NH*8 + 2

__device__ __forceinline__ float sigm(float x) { return 1.0f / (1.0f + expf(-x)); }

// ---------------------------------------------------------------------------
// Single fused kernel: 512 blocks x 128 threads, 2 sites/block.
// warp = tid>>5 (0..3); site si = warp>>1; pair-half w2 = warp&1.
//  Prologue: coalesced per-pair GEMV of the site's 514 gate rows (R6 pattern:
//            1 LDG.128 covers 4 consecutive fc_w rows' quarters, octet-shfl
//            reduce), forcing staging (+acos, ReLU(Ta)), activations,
//            cross-pair softmax.
//  Loop:     per-warp chunked scan (32 h per warp), zero block barriers,
//            single-parity smem buffer (2 syncwarp/chunk), reduced partials
//            kept in smem.
//  Epilogue: one __syncthreads, float2 write of both sites per timestep.
// ---------------------------------------------------------------------------
__global__ void __launch_bounds__(128)
waternet_kernel(const float* __restrict__ x,
                const float* __restrict__ xc,
                const float* __restrict__ fc_w,
                const float* __restrict__ fc_b,
                float* __restrict__ out) {
    __shared__ float4 sForc[2][NTP];              // 11776 B
    __shared__ float  sBuf[4][CH * RPITCH];       //  9216 B  (per warp)
    __shared__ float  sPart[4][NTP];              //  5888 B  (per-warp partials)
    __shared__ float4 sXc4[2][8];                 //   256 B
    __shared__ float  sW[2][512];                 //  4096 B  (GEMV results)
    __shared__ float  sMax[2][2], sSum[2][2], sQb[2];

    const int tid  = threadIdx.x;
    const int warp = tid >> 5;
    const int lane = tid & 31;
    const int si   = warp >> 1;          // site within block (0/1)
    const int w2   = warp & 1;           // half of the pair
    const int s0   = blockIdx.x * 2;
    const int s    = s0 + si;

    // ---- stage xc for both sites ----
    if (tid < 16) {
        const int ss = tid >> 3, q = tid & 7;
        sXc4[ss][q] = reinterpret_cast<const float4*>(xc + (s0 + ss) * NG)[q];
    }
    __syncthreads();

    // ---- forcing staging (per pair, t strided by 64) ----
    const float4* x4 = reinterpret_cast<const float4*>(x);
    for (int t = w2 * 32 + lane; t < NTP; t += 64) {
        float4 o = make_float4(0.f, 0.f, 0.f, 0.f);
        if (t < NT) {
            float4 xi = x4[t * NS + s];
            float P = xi.x, E = xi.y, T1 = xi.z, T2 = xi.w;
            float Ta = (T1 + T2) * 0.5f;
            bool valid  = (T1 < 0.0f) && (T2 > 0.0f);
            float denom = valid ? (T2 - T1) : 1.0f;
            float ratio = valid ? (T1 + T2) / denom : 0.0f;
            ratio = fminf(fmaxf(ratio, -0.999999f), 0.999999f);
            float rP = 1.0f - acosf(ratio) / 3.1415f;
            if (T1 >= 0.0f) rP = 1.0f;
            if (T2 <= 0.0f) rP = 0.0f;
            o.x = (1.0f - rP) * P;       // Ps
            o.y = rP * P;                // Pl
            o.z = fmaxf(Ta, 0.0f);       // ReLU(Ta)
            o.w = E;
        }
        sForc[si][t] = o;
    }

    // ---- coalesced GEMV for this site's gate rows ----
    {
        const float4* fw4 = reinterpret_cast<const float4*>(fc_w);
        const float4  xq  = sXc4[si][lane & 7];
        const int     b0  = w2 * 256 + lane;
        #pragma unroll 2
        for (int c = 0; c < 8; ++c) {
            float4 v[8];
            #pragma unroll
            for (int p = 0; p < 8; ++p) v[p] = fw4[c * 512 + b0 + p * 32];
            #pragma unroll
            for (int p = 0; p < 8; ++p) {
                float pr = v[p].x * xq.x + v[p].y * xq.y
                         + v[p].z * xq.z + v[p].w * xq.w;
                pr += __shfl_xor_sync(0xffffffffu, pr, 4);
                pr += __shfl_xor_sync(0xffffffffu, pr, 2);
                pr += __shfl_xor_sync(0xffffffffu, pr, 1);
                if ((lane & 7) == 0)
                    sW[si][c * 64 + w2 * 32 + p * 4 + (lane >> 3)] = pr;
            }
        }
        if (w2 == 1) {                   // qb row j = 513
            float4 v = fw4[513 * 8 + (lane & 7)];
            float pr = v.x * xq.x + v.y * xq.y + v.z * xq.z + v.w * xq.w;
            pr += __shfl_xor_sync(0xffffffffu, pr, 4);
            pr += __shfl_xor_sync(0xffffffffu, pr, 2);
            pr += __shfl_xor_sync(0xffffffffu, pr, 1);
            if (lane == 0)
                sQb[si] = fmaxf(pr + fc_b[513], 0.0f) * (1.0f / 64.0f);
        }
    }
    __syncthreads();

    // ---- activations (h = w2*32 + lane of site si) ----
    const int h = w2 * 32 + lane;
    float wv[8];
    #pragma unroll
    for (int c = 0; c < 8; ++c) wv[c] = sW[si][c * 64 + h] + fc_b[c * NH + h];

    const float gm   = expf(wv[0]) + 1.0f;
    const float nge  = -2.0f * sigm(wv[1]);
    const float go   = sigm(wv[2]);
    const float gl   = expf(2.0f * wv[3]);
    const float araw = wv[4];
    const float gb   = sigm(wv[5]);
    const float kb   = sigm(wv[6]) * 0.1f;
    const float gi   = sigm(wv[7]);
    const float kb1  = 1.0f - kb;

    // ---- softmax over the site's 64 h (cross-pair via smem) ----
    float m = araw;
    #pragma unroll
    for (int o = 16; o; o >>= 1) m = fmaxf(m, __shfl_xor_sync(0xffffffffu, m, o));
    if (lane == 0) sMax[si][w2] = m;
    __syncthreads();
    m = fmaxf(sMax[si][0], sMax[si][1]);
    float e = expf(araw - m);
    float ssum = e;
    #pragma unroll
    for (int o = 16; o; o >>= 1) ssum += __shfl_xor_sync(0xffffffffu, ssum, o);
    if (lane == 0) sSum[si][w2] = ssum;
    __syncthreads();
    const float ga = e / (sSum[si][0] + sSum[si][1]);

    const float chc  = go * (1.0f - gb) * ga - ga;   // coeff of Hc in y
    const float cg   = kb * ga;                      // coeff of g2 in y
    const float gogb = go * gb;

    // ---- sequential scan: per-warp, no block barriers ----
    float* buf = sBuf[warp];
    const float4* forc = sForc[si];
    float* part = sPart[warp];
    const int rt = lane >> 1;
    const int rq = lane & 1;

    float S0 = 0.0f, H0 = 0.0f, G0 = 0.0f;

    for (int c = 0; c < NCHUNK; ++c) {
        const float4* fp = forc + c * CH;
        float yv[CH];
        #pragma unroll
        for (int tt = 0; tt < CH; ++tt) {
            float4 f  = fp[tt];                      // broadcast LDS.128
            float Sm  = fminf(S0, f.z * gm);
            float At  = fmaf(f.w, nge, f.y * gi);    // Pl*gi - E*ge
            float H   = fmaxf(H0 + Sm + At, 0.0f);
            float Hc  = fminf(H, gl);
            float t1  = fmaf(-go, Hc, H);
            float g2  = fmaf(Hc, gogb, G0);
            H0 = fminf(t1, gl);
            G0 = g2 * kb1;
            S0 = (S0 - Sm) + f.x;
            float y = H * ga;
            y = fmaf(Hc, chc, y);
            y = fmaf(g2, cg, y);
            yv[tt] = y;
        }
        #pragma unroll
        for (int tt = 0; tt < CH; ++tt)
            buf[tt * RPITCH + lane] = yv[tt];        // burst, conflict-free
        __syncwarp();
        // transpose-reduce: 2 lanes per t, 16 each (float4 tree)
        const float4* rr = reinterpret_cast<const float4*>(buf + rt * RPITCH + rq * 16);
        float4 v0 = rr[0], v1 = rr[1], v2 = rr[2], v3 = rr[3];
        float p = (((v0.x + v0.y) + (v0.z + v0.w)) + ((v1.x + v1.y) + (v1.z + v1.w)))
                + (((v2.x + v2.y) + (v2.z + v2.w)) + ((v3.x + v3.y) + (v3.z + v3.w)));
        p += __shfl_xor_sync(0xffffffffu, p, 1);
        if (rq == 0) part[c * CH + rt] = p;          // partial -> smem
        __syncwarp();                                // reads done before reuse
    }

    // ---- epilogue: combine halves + qb, float2 store of both sites per t ----
    __syncthreads();
    const float qb0 = sQb[0], qb1 = sQb[1];
    for (int t = tid; t < NT; t += 128) {
        float2 o;
        o.x = sPart[0][t] + sPart[1][t] + qb0;
        o.y = sPart[2][t] + sPart[3][t] + qb1;
        *reinterpret_cast<float2*>(out + t * NS + s0) = o;
    }
}

// ---------------------------------------------------------------------------
extern "C" void kernel_launch(void* const* d_in, const int* in_sizes, int n_in,
                              void* d_out, int out_size) {
    const float* x    = (const float*)d_in[0];   // [NT, NS, 4]
    const float* xc   = (const float*)d_in[1];   // [NS, NG]
    const float* fc_w = (const float*)d_in[2];   // [NW, NG]
    const float* fc_b = (const float*)d_in[3];   // [NW]
    float* out = (float*)d_out;                  // [NT, NS]

    waternet_kernel<<<NS / 2, 128>>>(x, xc, fc_w, fc_b, out);
}

// round 14
// speedup vs baseline: 1.7887x; 1.0656x over previous
#include <cuda_runtime.h>
#include <math.h>

#define NT 365
#define NTP 368          // 23 chunks of 16
#define NCHUNK 23
#define CH 16
#define RPITCH 36        // reduce-buffer row pitch
#define FPITCH 369       // sForc row pitch (float4) - conflict-free staging
#define PPITCH 369       // sPart row pitch - conflict-free epilogue
#define NS 1024
#define NH 64
#define NG 32
#define NW 514
#define SPB 8            // sites per block
#define THREADS 512

__device__ __forceinline__ float sigm(float x) { return 1.0f / (1.0f + expf(-x)); }

// Dynamic smem layout (bytes):
//  sForc : SPB * FPITCH * 16          = 47232
//  sBuf  : 16 * CH * RPITCH * 4       = 36864  (overlaid with sFW during GEMV)
//  sPart : 16 * PPITCH * 4            = 23616
//  sXc   : SPB * NG * 4               = 1024
//  tail  : sQb[8] + sMax[8][2] + sSum[8][2] = 160
#define OFF_BUF   47232
#define OFF_PART  (OFF_BUF + 36864)
#define OFF_XC    (OFF_PART + 23616)
#define OFF_TAIL  (OFF_XC + 1024)
#define SMEM_TOTAL (OFF_TAIL + 160)

extern __shared__ __align__(16) char smemRaw[];

__global__ void __launch_bounds__(THREADS)
waternet_kernel(const float* __restrict__ x,
                const float* __restrict__ xc,
                const float* __restrict__ fc_w,
                const float* __restrict__ fc_b,
                float* __restrict__ out) {
    float4* sForc = reinterpret_cast<float4*>(smemRaw);                 // [SPB][FPITCH]
    float*  sBuf  = reinterpret_cast<float*>(smemRaw + OFF_BUF);        // [16][CH*RPITCH]
    float4* sFW4  = reinterpret_cast<float4*>(smemRaw + OFF_BUF);       // [64][9] overlay
    float*  sPart = reinterpret_cast<float*>(smemRaw + OFF_PART);       // [16][PPITCH]
    float*  sXc   = reinterpret_cast<float*>(smemRaw + OFF_XC);         // [SPB][NG]
    float*  sQb   = reinterpret_cast<float*>(smemRaw + OFF_TAIL);       // [8]
    float*  sMax  = sQb + 8;                                            // [8][2]
    float*  sSum  = sMax + 16;                                          // [8][2]

    const int tid  = threadIdx.x;
    const int warp = tid >> 5;          // 0..15
    const int lane = tid & 31;
    const int si   = warp >> 1;         // site in block 0..7
    const int w2   = warp & 1;          // pair half
    const int s0   = blockIdx.x * SPB;
    const int s    = s0 + si;
    const int h    = w2 * 32 + lane;    // 0..63

    // ---- stage xc for the 8 sites (coalesced) ----
    if (tid < SPB * NG) sXc[tid] = xc[s0 * NG + tid];

    // ---- forcing staging: COALESCED (8 consecutive sites per t) ----
    const float4* x4 = reinterpret_cast<const float4*>(x);
    for (int idx = tid; idx < NTP * SPB; idx += THREADS) {
        const int t  = idx >> 3;
        const int sl = idx & 7;
        float4 o = make_float4(0.f, 0.f, 0.f, 0.f);
        if (t < NT) {
            float4 xi = x4[t * NS + s0 + sl];       // full 128B lines
            float P = xi.x, E = xi.y, T1 = xi.z, T2 = xi.w;
            float Ta = (T1 + T2) * 0.5f;
            bool valid  = (T1 < 0.0f) && (T2 > 0.0f);
            float denom = valid ? (T2 - T1) : 1.0f;
            float ratio = valid ? (T1 + T2) / denom : 0.0f;
            ratio = fminf(fmaxf(ratio, -0.999999f), 0.999999f);
            float rP = 1.0f - acosf(ratio) / 3.1415f;
            if (T1 >= 0.0f) rP = 1.0f;
            if (T2 <= 0.0f) rP = 0.0f;
            o.x = (1.0f - rP) * P;      // Ps
            o.y = rP * P;               // Pl
            o.z = fmaxf(Ta, 0.0f);      // ReLU(Ta)
            o.w = E;
        }
        sForc[sl * FPITCH + t] = o;     // pitch 369 -> conflict-free
    }
    __syncthreads();

    // ---- xc of this thread's site into registers ----
    float4 xq[8];
    {
        const float4* xs4 = reinterpret_cast<const float4*>(sXc + si * NG);
        #pragma unroll
        for (int q = 0; q < 8; ++q) xq[q] = xs4[q];
    }

    // ---- GEMM: stage fc_w chunk (64 rows) in smem, all sites dot from it ----
    const float4* fw4 = reinterpret_cast<const float4*>(fc_w);
    float wv[8];
    #pragma unroll
    for (int c = 0; c < 8; ++c) {
        // stage rows [c*64, c*64+64): 512 float4, one per thread, coalesced
        {
            const int jl = tid >> 3;
            const int q  = tid & 7;
            sFW4[jl * 9 + q] = fw4[(c * 64 + jl) * 8 + q];
        }
        __syncthreads();
        float acc = 0.0f;
        #pragma unroll
        for (int q = 0; q < 8; ++q) {
            float4 v = sFW4[h * 9 + q];
            acc += v.x * xq[q].x + v.y * xq[q].y + v.z * xq[q].z + v.w * xq[q].w;
        }
        wv[c] = acc;
        __syncthreads();
    }
    #pragma unroll
    for (int c = 0; c < 8; ++c) wv[c] += fc_b[c * NH + h];

    // ---- qb: lanes 0..7 of warp 0 handle one site each ----
    if (warp == 0 && lane < SPB) {
        float acc = 0.0f;
        const float* xr = sXc + lane * NG;
        #pragma unroll
        for (int q = 0; q < 8; ++q) {
            float4 v = fw4[513 * 8 + q];            // L2-hot broadcast
            acc += v.x * xr[q * 4 + 0] + v.y * xr[q * 4 + 1]
                 + v.z * xr[q * 4 + 2] + v.w * xr[q * 4 + 3];
        }
        sQb[lane] = fmaxf(acc + fc_b[513], 0.0f) * (1.0f / 64.0f);
    }

    // ---- activations ----
    const float gm   = expf(wv[0]) + 1.0f;
    const float nge  = -2.0f * sigm(wv[1]);
    const float go   = sigm(wv[2]);
    const float gl   = expf(2.0f * wv[3]);
    const float araw = wv[4];
    const float gb   = sigm(wv[5]);
    const float kb   = sigm(wv[6]) * 0.1f;
    const float gi   = sigm(wv[7]);
    const float kb1  = 1.0f - kb;

    // ---- softmax over the site's 64 h (cross-pair via smem) ----
    float m = araw;
    #pragma unroll
    for (int o = 16; o; o >>= 1) m = fmaxf(m, __shfl_xor_sync(0xffffffffu, m, o));
    if (lane == 0) sMax[si * 2 + w2] = m;
    __syncthreads();
    m = fmaxf(sMax[si * 2], sMax[si * 2 + 1]);
    float e = expf(araw - m);
    float ssum = e;
    #pragma unroll
    for (int o = 16; o; o >>= 1) ssum += __shfl_xor_sync(0xffffffffu, ssum, o);
    if (lane == 0) sSum[si * 2 + w2] = ssum;
    __syncthreads();
    const float ga = e / (sSum[si * 2] + sSum[si * 2 + 1]);

    const float chc  = go * (1.0f - gb) * ga - ga;
    const float cg   = kb * ga;
    const float gogb = go * gb;

    // ---- sequential scan: per-warp, no block barriers ----
    float* buf = sBuf + warp * (CH * RPITCH);
    const float4* forc = sForc + si * FPITCH;
    float* part = sPart + warp * PPITCH;
    const int rt = lane >> 1;
    const int rq = lane & 1;

    float S0 = 0.0f, H0 = 0.0f, G0 = 0.0f;

    for (int c = 0; c < NCHUNK; ++c) {
        const float4* fp = forc + c * CH;
        float yv[CH];
        #pragma unroll
        for (int tt = 0; tt < CH; ++tt) {
            float4 f  = fp[tt];                      // broadcast LDS.128
            float Sm  = fminf(S0, f.z * gm);
            float At  = fmaf(f.w, nge, f.y * gi);    // Pl*gi - E*ge
            float H   = fmaxf(H0 + Sm + At, 0.0f);
            float Hc  = fminf(H, gl);
            float t1  = fmaf(-go, Hc, H);
            float g2  = fmaf(Hc, gogb, G0);
            H0 = fminf(t1, gl);
            G0 = g2 * kb1;
            S0 = (S0 - Sm) + f.x;
            float y = H * ga;
            y = fmaf(Hc, chc, y);
            y = fmaf(g2, cg, y);
            yv[tt] = y;
        }
        #pragma unroll
        for (int tt = 0; tt < CH; ++tt)
            buf[tt * RPITCH + lane] = yv[tt];        // burst, conflict-free
        __syncwarp();
        const float4* rr = reinterpret_cast<const float4*>(buf + rt * RPITCH + rq * 16);
        float4 v0 = rr[0], v1 = rr[1], v2 = rr[2], v3 = rr[3];
        float p = (((v0.x + v0.y) + (v0.z + v0.w)) + ((v1.x + v1.y) + (v1.z + v1.w)))
                + (((v2.x + v2.y) + (v2.z + v2.w)) + ((v3.x + v3.y) + (v3.z + v3.w)));
        p += __shfl_xor_sync(0xffffffffu, p, 1);
        if (rq == 0) part[c * CH + rt] = p;
        __syncwarp();
    }

    // ---- epilogue: combine pair halves + qb; near-coalesced stores ----
    __syncthreads();
    for (int idx = tid; idx < NT * SPB; idx += THREADS) {
        const int t  = idx >> 3;
        const int sl = idx & 7;
        const float v = sPart[(2 * sl) * PPITCH + t]
                      + sPart[(2 * sl + 1) * PPITCH + t]
                      + sQb[sl];
        out[t * NS + s0 + sl] = v;
    }
}

// ---------------------------------------------------------------------------
extern "C" void kernel_launch(void* const* d_in, const int* in_sizes, int n_in,
                              void* d_out, int out_size) {
    const float* x    = (const float*)d_in[0];   // [NT, NS, 4]
    const float* xc   = (const float*)d_in[1];   // [NS, NG]
    const float* fc_w = (const float*)d_in[2];   // [NW, NG]
    const float* fc_b = (const float*)d_in[3];   // [NW]
    float* out = (float*)d_out;                  // [NT, NS]

    static int configured = 0;
    if (!configured) {
        cudaFuncSetAttribute(waternet_kernel,
                             cudaFuncAttributeMaxDynamicSharedMemorySize,
                             SMEM_TOTAL);
        configured = 1;
    }
    waternet_kernel<<<NS / SPB, THREADS, SMEM_TOTAL>>>(x, xc, fc_w, fc_b, out);
}